// round 3
// baseline (speedup 1.0000x reference)
#include <cuda_runtime.h>
#include <cuda_bf16.h>
#include <cstdint>

// Problem constants (fixed shapes for this problem instance)
#define MAXN 50000
#define MAXE 800000
#define FEAT 256          // IN_C = HID = 256 (and 2*OUT_C = 256)
#define OUTC 128

// ---------------------------------------------------------------------------
// Static device scratch (no dynamic allocation allowed)
// ---------------------------------------------------------------------------
__device__ float g_h0[(size_t)MAXN * FEAT];   // GEMM outputs (reused for layer 2)
__device__ float g_h [(size_t)MAXN * FEAT];   // post-aggregation hidden (after relu)
__device__ float g_dinv[MAXN];
__device__ int   g_count[MAXN];
__device__ int   g_rowptr[MAXN + 1];
__device__ int   g_cursor[MAXN];
__device__ int   g_col[MAXE];
__device__ float g_val[MAXE];
__device__ int   g_bsums[64];
__device__ int   g_is64;

// ---------------------------------------------------------------------------
// Edge-index dtype detection (int64 vs int32; JAX may truncate int64->int32)
// ---------------------------------------------------------------------------
__global__ void detect_kernel(const void* ei, int n, int E)
{
    if (threadIdx.x == 0 && blockIdx.x == 0) {
        const long long* p64 = (const long long*)ei;
        int m = 2048;
        if (E < m) m = E;  // E int64s always available in either interpretation
        int ok = 1;
        for (int i = 0; i < m; ++i) {
            long long v = p64[i];
            if (v < 0 || v >= (long long)n) { ok = 0; break; }
        }
        g_is64 = ok;
    }
}

__device__ __forceinline__ int edge_at(const void* ei, int idx)
{
    if (g_is64) return (int)((const long long*)ei)[idx];
    return ((const int*)ei)[idx];
}

// ---------------------------------------------------------------------------
// CSR build
// ---------------------------------------------------------------------------
__global__ void init_kernel(int n)
{
    int i = blockIdx.x * blockDim.x + threadIdx.x;
    if (i < n) g_count[i] = 0;
}

__global__ void count_kernel(const void* ei, int E)
{
    int e = blockIdx.x * blockDim.x + threadIdx.x;
    if (e < E) {
        int d = edge_at(ei, E + e);   // dst row of edge_index
        atomicAdd(&g_count[d], 1);
    }
}

__global__ void dinv_kernel(int n)
{
    int i = blockIdx.x * blockDim.x + threadIdx.x;
    if (i < n) g_dinv[i] = rsqrtf((float)g_count[i] + 1.0f);  // +1 = self loop
}

// exclusive scan of g_count -> g_rowptr (3 kernels)
__global__ void scan_block_kernel(int n)
{
    __shared__ int s[1024];
    int b = blockIdx.x;
    int i = b * 1024 + threadIdx.x;
    int v = (i < n) ? g_count[i] : 0;
    s[threadIdx.x] = v;
    __syncthreads();
    for (int off = 1; off < 1024; off <<= 1) {
        int t = (threadIdx.x >= off) ? s[threadIdx.x - off] : 0;
        __syncthreads();
        s[threadIdx.x] += t;
        __syncthreads();
    }
    if (i < n) g_rowptr[i] = s[threadIdx.x] - v;   // exclusive within block
    if (threadIdx.x == 1023) g_bsums[b] = s[1023];
}

__global__ void scan_sums_kernel(int nb)
{
    if (threadIdx.x == 0 && blockIdx.x == 0) {
        int run = 0;
        for (int b = 0; b < nb; ++b) { int t = g_bsums[b]; g_bsums[b] = run; run += t; }
    }
}

__global__ void scan_add_kernel(int n, int E)
{
    int i = blockIdx.x * blockDim.x + threadIdx.x;
    if (i < n) {
        int r = g_rowptr[i] + g_bsums[i / 1024];
        g_rowptr[i] = r;
        g_cursor[i] = r;
    }
    if (i == 0) g_rowptr[n] = E;
}

__global__ void scatter_kernel(const void* ei, int E)
{
    int e = blockIdx.x * blockDim.x + threadIdx.x;
    if (e < E) {
        int s = edge_at(ei, e);
        int d = edge_at(ei, E + e);
        int p = atomicAdd(&g_cursor[d], 1);
        g_col[p] = s;
        g_val[p] = g_dinv[s] * g_dinv[d];
    }
}

// ---------------------------------------------------------------------------
// SGEMM: C[m, coff+bn..] = A[M x 256] @ B[256 x Ncols], fp32, K = 256 fixed.
// BM=128, BN=64, BK=16, 256 threads, 8x4 per thread.
// ---------------------------------------------------------------------------
#define BM 128
#define BN 64
#define BK 16

__global__ __launch_bounds__(256) void sgemm_kernel(
    const float* __restrict__ A, const float* __restrict__ B,
    float* __restrict__ C, int M, int ldb, int ldc, int coff)
{
    const int K = 256;
    __shared__ float As[BK][BM];
    __shared__ float Bs[BK][BN];

    int tid = threadIdx.x;
    int bm = blockIdx.x * BM;
    int bn = blockIdx.y * BN;

    int ty = tid >> 4;        // 0..15
    int tx = tid & 15;        // 0..15
    int mreg = ty * 8;
    int nreg = tx * 4;

    float acc[8][4];
#pragma unroll
    for (int i = 0; i < 8; ++i)
#pragma unroll
        for (int j = 0; j < 4; ++j) acc[i][j] = 0.0f;

    for (int k0 = 0; k0 < K; k0 += BK) {
        // load A tile (128x16), transposed into As[k][m]
#pragma unroll
        for (int t = 0; t < 2; ++t) {
            int f = tid + t * 256;
            int row = f >> 2;
            int kq = (f & 3) * 4;
            float4 v;
            int grow = bm + row;
            if (grow < M) v = *reinterpret_cast<const float4*>(&A[(size_t)grow * K + k0 + kq]);
            else v = make_float4(0.f, 0.f, 0.f, 0.f);
            As[kq + 0][row] = v.x;
            As[kq + 1][row] = v.y;
            As[kq + 2][row] = v.z;
            As[kq + 3][row] = v.w;
        }
        // load B tile (16x64)
        {
            int row = tid >> 4;
            int c4 = (tid & 15) * 4;
            float4 v = *reinterpret_cast<const float4*>(&B[(size_t)(k0 + row) * ldb + bn + c4]);
            *reinterpret_cast<float4*>(&Bs[row][c4]) = v;
        }
        __syncthreads();

#pragma unroll
        for (int k = 0; k < BK; ++k) {
            float4 a0 = *reinterpret_cast<const float4*>(&As[k][mreg]);
            float4 a1 = *reinterpret_cast<const float4*>(&As[k][mreg + 4]);
            float4 b0 = *reinterpret_cast<const float4*>(&Bs[k][nreg]);
            float ra[8] = {a0.x, a0.y, a0.z, a0.w, a1.x, a1.y, a1.z, a1.w};
            float rb[4] = {b0.x, b0.y, b0.z, b0.w};
#pragma unroll
            for (int i = 0; i < 8; ++i)
#pragma unroll
                for (int j = 0; j < 4; ++j) acc[i][j] += ra[i] * rb[j];
        }
        __syncthreads();
    }

#pragma unroll
    for (int i = 0; i < 8; ++i) {
        int grow = bm + mreg + i;
        if (grow < M) {
#pragma unroll
            for (int j = 0; j < 4; ++j)
                C[(size_t)grow * ldc + coff + bn + nreg + j] = acc[i][j];
        }
    }
}

// ---------------------------------------------------------------------------
// Aggregation: one block per node, 256 threads = 256 feature channels.
// out[i][c] = sum_{e in CSR row i} val[e]*h[col[e]][c] + dinv[i]^2*h[i][c]
// Layer 1 adds b1 + relu; layer 2 splits into mu / logstd halves of d_out.
// ---------------------------------------------------------------------------
__global__ void agg1_kernel(const float* __restrict__ b1, int n)
{
    int i = blockIdx.x;
    int c = threadIdx.x;
    float di = g_dinv[i];
    float acc0 = di * di * g_h0[(size_t)i * FEAT + c];
    float acc1 = 0.0f;
    int e0 = g_rowptr[i], e1 = g_rowptr[i + 1];
    int e = e0;
    for (; e + 1 < e1; e += 2) {
        int s0 = g_col[e];     float w0 = g_val[e];
        int s1 = g_col[e + 1]; float w1 = g_val[e + 1];
        acc0 += w0 * g_h0[(size_t)s0 * FEAT + c];
        acc1 += w1 * g_h0[(size_t)s1 * FEAT + c];
    }
    if (e < e1) {
        int s = g_col[e]; float w = g_val[e];
        acc0 += w * g_h0[(size_t)s * FEAT + c];
    }
    float r = acc0 + acc1 + b1[c];
    g_h[(size_t)i * FEAT + c] = fmaxf(r, 0.0f);
}

__global__ void agg2_kernel(const float* __restrict__ bmu,
                            const float* __restrict__ bls,
                            float* __restrict__ out, int n)
{
    int i = blockIdx.x;
    int c = threadIdx.x;
    float di = g_dinv[i];
    float acc0 = di * di * g_h0[(size_t)i * FEAT + c];
    float acc1 = 0.0f;
    int e0 = g_rowptr[i], e1 = g_rowptr[i + 1];
    int e = e0;
    for (; e + 1 < e1; e += 2) {
        int s0 = g_col[e];     float w0 = g_val[e];
        int s1 = g_col[e + 1]; float w1 = g_val[e + 1];
        acc0 += w0 * g_h0[(size_t)s0 * FEAT + c];
        acc1 += w1 * g_h0[(size_t)s1 * FEAT + c];
    }
    if (e < e1) {
        int s = g_col[e]; float w = g_val[e];
        acc0 += w * g_h0[(size_t)s * FEAT + c];
    }
    float r = acc0 + acc1;
    if (c < OUTC) {
        out[(size_t)i * OUTC + c] = r + bmu[c];
    } else {
        out[(size_t)n * OUTC + (size_t)i * OUTC + (c - OUTC)] = r + bls[c - OUTC];
    }
}

// ---------------------------------------------------------------------------
// Launch
// ---------------------------------------------------------------------------
extern "C" void kernel_launch(void* const* d_in, const int* in_sizes, int n_in,
                              void* d_out, int out_size)
{
    const float* x    = (const float*)d_in[0];
    const void*  ei   = d_in[1];                 // int64 or int32, detected on device
    const float* W1   = (const float*)d_in[2];
    const float* b1   = (const float*)d_in[3];
    const float* Wmu  = (const float*)d_in[4];
    const float* bmu  = (const float*)d_in[5];
    const float* Wls  = (const float*)d_in[6];
    const float* bls  = (const float*)d_in[7];
    float* out = (float*)d_out;

    int n = in_sizes[0] / FEAT;      // 50000
    int E = in_sizes[1] / 2;         // 800000

    int TB = 256;
    int gN = (n + TB - 1) / TB;
    int gE = (E + TB - 1) / TB;
    int nb = (n + 1023) / 1024;

    // resolve scratch pointers needed by sgemm (A/C args)
    float* h0; cudaGetSymbolAddress((void**)&h0, g_h0);
    float* h;  cudaGetSymbolAddress((void**)&h,  g_h);

    // --- CSR build ---
    detect_kernel<<<1, 32>>>(ei, n, E);
    init_kernel<<<gN, TB>>>(n);
    count_kernel<<<gE, TB>>>(ei, E);
    dinv_kernel<<<gN, TB>>>(n);
    scan_block_kernel<<<nb, 1024>>>(n);
    scan_sums_kernel<<<1, 32>>>(nb);
    scan_add_kernel<<<gN, TB>>>(n, E);
    scatter_kernel<<<gE, TB>>>(ei, E);

    // --- Layer 1: h0 = x @ W1 ; h = relu(agg(h0) + b1) ---
    dim3 g1((n + BM - 1) / BM, FEAT / BN);
    sgemm_kernel<<<g1, 256>>>(x, W1, h0, n, FEAT, FEAT, 0);
    agg1_kernel<<<n, FEAT>>>(b1, n);

    // --- Layer 2: h0[:, :128] = h @ W_mu ; h0[:, 128:] = h @ W_ls ---
    dim3 g2((n + BM - 1) / BM, OUTC / BN);
    sgemm_kernel<<<g2, 256>>>(h, Wmu, h0, n, OUTC, FEAT, 0);
    sgemm_kernel<<<g2, 256>>>(h, Wls, h0, n, OUTC, FEAT, OUTC);

    // --- Final aggregation straight into d_out (mu | logstd) ---
    agg2_kernel<<<n, FEAT>>>(bmu, bls, out, n);
}

// round 5
// speedup vs baseline: 1.3285x; 1.3285x over previous
#include <cuda_runtime.h>
#include <cuda_bf16.h>
#include <cstdint>

// Problem constants (fixed shapes for this problem instance)
#define MAXN 50000
#define MAXE 800000
#define FEAT 256          // IN_C = HID = 256 (and 2*OUT_C = 256)
#define OUTC 128

// ---------------------------------------------------------------------------
// Static device scratch (no dynamic allocation allowed)
// ---------------------------------------------------------------------------
__device__ float g_h0[(size_t)MAXN * FEAT];          // GEMM outputs (fp32, agg input)
__device__ __nv_bfloat16 g_xhi[(size_t)MAXN * FEAT]; // split x
__device__ __nv_bfloat16 g_xlo[(size_t)MAXN * FEAT];
__device__ __nv_bfloat16 g_hhi[(size_t)MAXN * FEAT]; // split hidden (post agg1)
__device__ __nv_bfloat16 g_hlo[(size_t)MAXN * FEAT];
__device__ __nv_bfloat16 g_B1hi[FEAT * FEAT];        // W1^T split  [n][k]
__device__ __nv_bfloat16 g_B1lo[FEAT * FEAT];
__device__ __nv_bfloat16 g_B2hi[FEAT * FEAT];        // [Wmu|Wls]^T split [n][k]
__device__ __nv_bfloat16 g_B2lo[FEAT * FEAT];
__device__ float g_dinv[MAXN];
__device__ int   g_count[MAXN];
__device__ int   g_rowptr[MAXN + 1];
__device__ int   g_cursor[MAXN];
__device__ int   g_col[MAXE];
__device__ float g_val[MAXE];
__device__ int   g_bsums[64];
__device__ int   g_is64;

// ---------------------------------------------------------------------------
// PTX helpers: ldmatrix + bf16 mma (portable to compute_103 virtual arch)
// ---------------------------------------------------------------------------
__device__ __forceinline__ uint32_t smem_u32(const void* p)
{
    uint32_t a;
    asm("{ .reg .u64 t; cvta.to.shared.u64 t, %1; cvt.u32.u64 %0, t; }"
        : "=r"(a) : "l"(p));
    return a;
}

#define LDSM_X4(r, addr)                                                        \
    asm volatile("ldmatrix.sync.aligned.m8n8.x4.shared.b16 {%0,%1,%2,%3}, [%4];"\
        : "=r"((r)[0]), "=r"((r)[1]), "=r"((r)[2]), "=r"((r)[3])                \
        : "r"(addr))

#define MMA_BF16(c, a, b0, b1)                                                  \
    asm volatile("mma.sync.aligned.m16n8k16.row.col.f32.bf16.bf16.f32 "         \
        "{%0,%1,%2,%3}, {%4,%5,%6,%7}, {%8,%9}, {%0,%1,%2,%3};"                 \
        : "+f"((c)[0]), "+f"((c)[1]), "+f"((c)[2]), "+f"((c)[3])                \
        : "r"((a)[0]), "r"((a)[1]), "r"((a)[2]), "r"((a)[3]),                   \
          "r"(b0), "r"(b1))

#define SWZ128(o) ((o) ^ (((o) >> 3) & 0x70))

// ---------------------------------------------------------------------------
// Edge-index dtype detection (int64 vs int32; JAX may truncate int64->int32)
// ---------------------------------------------------------------------------
__global__ void detect_kernel(const void* ei, int n, int E)
{
    if (threadIdx.x == 0 && blockIdx.x == 0) {
        const long long* p64 = (const long long*)ei;
        int m = 2048;
        if (E < m) m = E;
        int ok = 1;
        for (int i = 0; i < m; ++i) {
            long long v = p64[i];
            if (v < 0 || v >= (long long)n) { ok = 0; break; }
        }
        g_is64 = ok;
    }
}

__device__ __forceinline__ int edge_at(const void* ei, int idx)
{
    if (g_is64) return (int)((const long long*)ei)[idx];
    return ((const int*)ei)[idx];
}

// ---------------------------------------------------------------------------
// CSR build
// ---------------------------------------------------------------------------
__global__ void init_kernel(int n)
{
    int i = blockIdx.x * blockDim.x + threadIdx.x;
    if (i < n) g_count[i] = 0;
}

__global__ void count_kernel(const void* ei, int E)
{
    int e = blockIdx.x * blockDim.x + threadIdx.x;
    if (e < E) {
        int d = edge_at(ei, E + e);
        atomicAdd(&g_count[d], 1);
    }
}

__global__ void dinv_kernel(int n)
{
    int i = blockIdx.x * blockDim.x + threadIdx.x;
    if (i < n) g_dinv[i] = rsqrtf((float)g_count[i] + 1.0f);
}

__global__ void scan_block_kernel(int n)
{
    __shared__ int s[1024];
    int b = blockIdx.x;
    int i = b * 1024 + threadIdx.x;
    int v = (i < n) ? g_count[i] : 0;
    s[threadIdx.x] = v;
    __syncthreads();
    for (int off = 1; off < 1024; off <<= 1) {
        int t = (threadIdx.x >= off) ? s[threadIdx.x - off] : 0;
        __syncthreads();
        s[threadIdx.x] += t;
        __syncthreads();
    }
    if (i < n) g_rowptr[i] = s[threadIdx.x] - v;
    if (threadIdx.x == 1023) g_bsums[b] = s[1023];
}

__global__ void scan_sums_kernel(int nb)
{
    if (threadIdx.x == 0 && blockIdx.x == 0) {
        int run = 0;
        for (int b = 0; b < nb; ++b) { int t = g_bsums[b]; g_bsums[b] = run; run += t; }
    }
}

__global__ void scan_add_kernel(int n, int E)
{
    int i = blockIdx.x * blockDim.x + threadIdx.x;
    if (i < n) {
        int r = g_rowptr[i] + g_bsums[i / 1024];
        g_rowptr[i] = r;
        g_cursor[i] = r;
    }
    if (i == 0) g_rowptr[n] = E;
}

__global__ void scatter_kernel(const void* ei, int E)
{
    int e = blockIdx.x * blockDim.x + threadIdx.x;
    if (e < E) {
        int s = edge_at(ei, e);
        int d = edge_at(ei, E + e);
        int p = atomicAdd(&g_cursor[d], 1);
        g_col[p] = s;
        g_val[p] = g_dinv[s] * g_dinv[d];
    }
}

// ---------------------------------------------------------------------------
// fp32 -> bf16 hi/lo split kernels
// ---------------------------------------------------------------------------
__global__ void conv_split_kernel(const float* __restrict__ a,
                                  __nv_bfloat16* __restrict__ hi,
                                  __nv_bfloat16* __restrict__ lo, int n)
{
    int i = blockIdx.x * blockDim.x + threadIdx.x;
    if (i < n) {
        float v = a[i];
        __nv_bfloat16 h = __float2bfloat16(v);
        hi[i] = h;
        lo[i] = __float2bfloat16(v - __bfloat162float(h));
    }
}

// W1 [k=256][n=256] row-major -> B1 [n][k] bf16 hi/lo
__global__ void convW1_kernel(const float* __restrict__ W1)
{
    int idx = blockIdx.x * blockDim.x + threadIdx.x;   // 65536
    int k = idx >> 8, n = idx & 255;
    float v = W1[idx];
    __nv_bfloat16 h = __float2bfloat16(v);
    g_B1hi[n * FEAT + k] = h;
    g_B1lo[n * FEAT + k] = __float2bfloat16(v - __bfloat162float(h));
}

// [Wmu | Wls] concat -> B2 [n(0..255)][k] hi/lo
__global__ void convW2_kernel(const float* __restrict__ Wmu, const float* __restrict__ Wls)
{
    int idx = blockIdx.x * blockDim.x + threadIdx.x;   // 65536
    int k = idx >> 8, n = idx & 255;
    float v = (n < OUTC) ? Wmu[k * OUTC + n] : Wls[k * OUTC + (n - OUTC)];
    __nv_bfloat16 h = __float2bfloat16(v);
    g_B2hi[n * FEAT + k] = h;
    g_B2lo[n * FEAT + k] = __float2bfloat16(v - __bfloat162float(h));
}

// ---------------------------------------------------------------------------
// HMMA GEMM: C[M x 256] = (Ahi+Alo) @ (Bhi+Blo)^T  (B stored [n][k])
// CTA tile 128x128, BK=64, 3-term bf16 split via mma.m16n8k16, fp32 accum.
// 8 warps: warp_m = w&3 (32 rows), warp_n = w>>2 (64 cols).
// grid = (ceil(M/128), 2). Dynamic smem = 64 KB (4 x 16KB SW128 tiles).
// ---------------------------------------------------------------------------
#define GBM 128
#define GBN 128
#define GBK 64
#define GEMM_SMEM 65536

__global__ __launch_bounds__(256, 1) void gemm_mma_kernel(
    const __nv_bfloat16* __restrict__ Ahi, const __nv_bfloat16* __restrict__ Alo,
    const __nv_bfloat16* __restrict__ Bhi, const __nv_bfloat16* __restrict__ Blo,
    float* __restrict__ C, int M)
{
    extern __shared__ char smem[];
    const int SM_AH = 0;
    const int SM_AL = 16384;
    const int SM_BH = 32768;
    const int SM_BL = 49152;

    uint32_t sb = smem_u32(smem);
    int tid  = threadIdx.x;
    int lane = tid & 31;
    int w    = tid >> 5;
    int bm = blockIdx.x * GBM;
    int bn = blockIdx.y * GBN;
    int wm = (w & 3) * 32;
    int wn = (w >> 2) * 64;

    // Unswizzled byte offsets inside a tile for ldmatrix lane addresses.
    // A m16k16 frag (x4): matrices {r0-7 klo, r8-15 klo, r0-7 khi, r8-15 khi}
    int a_pre[2];
    {
        int r = wm + ((lane >> 3) & 1) * 8 + (lane & 7);
        int kb = (lane >> 4) * 16;
        a_pre[0] = r * 128 + kb;
        a_pre[1] = (r + 16) * 128 + kb;
    }
    // B n16k16 (x4 -> two n8k16 frags): {n0-7 klo, n0-7 khi, n8-15 klo, n8-15 khi}
    int b_pre[4];
    {
        int r = wn + ((lane >> 4) & 1) * 8 + (lane & 7);
        int kb = ((lane >> 3) & 1) * 16;
#pragma unroll
        for (int nf2 = 0; nf2 < 4; ++nf2)
            b_pre[nf2] = (r + nf2 * 16) * 128 + kb;
    }

    float acc[2][8][4];
#pragma unroll
    for (int i = 0; i < 2; ++i)
#pragma unroll
        for (int j = 0; j < 8; ++j)
#pragma unroll
            for (int q = 0; q < 4; ++q) acc[i][j][q] = 0.0f;

    for (int kc = 0; kc < 4; ++kc) {
        int k0 = kc * GBK;
        // cooperative tile loads: 1024 16B chunks per array, 256 threads
#pragma unroll
        for (int t = 0; t < 4; ++t) {
            int idx = tid + t * 256;          // 0..1023
            int row = idx >> 3;               // 0..127
            int ch  = idx & 7;                // 16B chunk within 128B row
            uint32_t off = SWZ128(row * 128 + ch * 16);
            int gr = bm + row;
            float4 vh, vl;
            if (gr < M) {
                vh = *(const float4*)(Ahi + (size_t)gr * FEAT + k0 + ch * 8);
                vl = *(const float4*)(Alo + (size_t)gr * FEAT + k0 + ch * 8);
            } else {
                vh = make_float4(0.f, 0.f, 0.f, 0.f);
                vl = vh;
            }
            *(float4*)(smem + SM_AH + off) = vh;
            *(float4*)(smem + SM_AL + off) = vl;
            int gn = bn + row;                // < 256 always
            float4 wh = *(const float4*)(Bhi + (size_t)gn * FEAT + k0 + ch * 8);
            float4 wl = *(const float4*)(Blo + (size_t)gn * FEAT + k0 + ch * 8);
            *(float4*)(smem + SM_BH + off) = wh;
            *(float4*)(smem + SM_BL + off) = wl;
        }
        __syncthreads();

#pragma unroll
        for (int ks = 0; ks < 4; ++ks) {
            int kb = ks * 32;
            uint32_t ah[2][4], al[2][4], bh[4][4], bl[4][4];
#pragma unroll
            for (int mf = 0; mf < 2; ++mf) {
                uint32_t o = SWZ128(a_pre[mf] + kb);
                LDSM_X4(ah[mf], sb + SM_AH + o);
                LDSM_X4(al[mf], sb + SM_AL + o);
            }
#pragma unroll
            for (int nf2 = 0; nf2 < 4; ++nf2) {
                uint32_t o = SWZ128(b_pre[nf2] + kb);
                LDSM_X4(bh[nf2], sb + SM_BH + o);
                LDSM_X4(bl[nf2], sb + SM_BL + o);
            }
#pragma unroll
            for (int mf = 0; mf < 2; ++mf) {
#pragma unroll
                for (int nf2 = 0; nf2 < 4; ++nf2) {
                    MMA_BF16(acc[mf][nf2 * 2],     ah[mf], bh[nf2][0], bh[nf2][1]);
                    MMA_BF16(acc[mf][nf2 * 2 + 1], ah[mf], bh[nf2][2], bh[nf2][3]);
                    MMA_BF16(acc[mf][nf2 * 2],     ah[mf], bl[nf2][0], bl[nf2][1]);
                    MMA_BF16(acc[mf][nf2 * 2 + 1], ah[mf], bl[nf2][2], bl[nf2][3]);
                    MMA_BF16(acc[mf][nf2 * 2],     al[mf], bh[nf2][0], bh[nf2][1]);
                    MMA_BF16(acc[mf][nf2 * 2 + 1], al[mf], bh[nf2][2], bh[nf2][3]);
                }
            }
        }
        __syncthreads();
    }

    // epilogue: accumulator lane layout -> direct gmem stores (float2)
    int g  = lane >> 2;
    int cc = (lane & 3) * 2;
#pragma unroll
    for (int mf = 0; mf < 2; ++mf) {
#pragma unroll
        for (int nf = 0; nf < 8; ++nf) {
            int row = bm + wm + mf * 16 + g;
            int col = bn + wn + nf * 8 + cc;
            if (row < M) {
                float2 v0 = make_float2(acc[mf][nf][0], acc[mf][nf][1]);
                *(float2*)&C[(size_t)row * FEAT + col] = v0;
            }
            if (row + 8 < M) {
                float2 v1 = make_float2(acc[mf][nf][2], acc[mf][nf][3]);
                *(float2*)&C[(size_t)(row + 8) * FEAT + col] = v1;
            }
        }
    }
}

// ---------------------------------------------------------------------------
// Aggregation: one block per node, 256 threads = 256 feature channels.
// out[i][c] = sum_{e in CSR row i} val[e]*h[col[e]][c] + dinv[i]^2*h[i][c]
// agg1 adds b1 + relu and writes bf16 hi/lo for the next GEMM.
// agg2 splits into mu / logstd halves of d_out.
// ---------------------------------------------------------------------------
__global__ void agg1_kernel(const float* __restrict__ b1, int n)
{
    int i = blockIdx.x;
    int c = threadIdx.x;
    float di = g_dinv[i];
    float acc0 = di * di * g_h0[(size_t)i * FEAT + c];
    float acc1 = 0.0f;
    int e0 = g_rowptr[i], e1 = g_rowptr[i + 1];
    int e = e0;
    for (; e + 1 < e1; e += 2) {
        int s0 = g_col[e];     float w0 = g_val[e];
        int s1 = g_col[e + 1]; float w1 = g_val[e + 1];
        acc0 += w0 * g_h0[(size_t)s0 * FEAT + c];
        acc1 += w1 * g_h0[(size_t)s1 * FEAT + c];
    }
    if (e < e1) {
        int s = g_col[e]; float w = g_val[e];
        acc0 += w * g_h0[(size_t)s * FEAT + c];
    }
    float r = fmaxf(acc0 + acc1 + b1[c], 0.0f);
    __nv_bfloat16 h = __float2bfloat16(r);
    g_hhi[(size_t)i * FEAT + c] = h;
    g_hlo[(size_t)i * FEAT + c] = __float2bfloat16(r - __bfloat162float(h));
}

__global__ void agg2_kernel(const float* __restrict__ bmu,
                            const float* __restrict__ bls,
                            float* __restrict__ out, int n)
{
    int i = blockIdx.x;
    int c = threadIdx.x;
    float di = g_dinv[i];
    float acc0 = di * di * g_h0[(size_t)i * FEAT + c];
    float acc1 = 0.0f;
    int e0 = g_rowptr[i], e1 = g_rowptr[i + 1];
    int e = e0;
    for (; e + 1 < e1; e += 2) {
        int s0 = g_col[e];     float w0 = g_val[e];
        int s1 = g_col[e + 1]; float w1 = g_val[e + 1];
        acc0 += w0 * g_h0[(size_t)s0 * FEAT + c];
        acc1 += w1 * g_h0[(size_t)s1 * FEAT + c];
    }
    if (e < e1) {
        int s = g_col[e]; float w = g_val[e];
        acc0 += w * g_h0[(size_t)s * FEAT + c];
    }
    float r = acc0 + acc1;
    if (c < OUTC) {
        out[(size_t)i * OUTC + c] = r + bmu[c];
    } else {
        out[(size_t)n * OUTC + (size_t)i * OUTC + (c - OUTC)] = r + bls[c - OUTC];
    }
}

// ---------------------------------------------------------------------------
// Launch
// ---------------------------------------------------------------------------
extern "C" void kernel_launch(void* const* d_in, const int* in_sizes, int n_in,
                              void* d_out, int out_size)
{
    const float* x    = (const float*)d_in[0];
    const void*  ei   = d_in[1];
    const float* W1   = (const float*)d_in[2];
    const float* b1   = (const float*)d_in[3];
    const float* Wmu  = (const float*)d_in[4];
    const float* bmu  = (const float*)d_in[5];
    const float* Wls  = (const float*)d_in[6];
    const float* bls  = (const float*)d_in[7];
    float* out = (float*)d_out;

    int n = in_sizes[0] / FEAT;      // 50000
    int E = in_sizes[1] / 2;         // 800000

    int TB = 256;
    int gN = (n + TB - 1) / TB;
    int gE = (E + TB - 1) / TB;
    int nb = (n + 1023) / 1024;

    float* h0;  cudaGetSymbolAddress((void**)&h0,  g_h0);
    __nv_bfloat16 *xhi, *xlo, *hhi, *hlo, *b1hi, *b1lo, *b2hi, *b2lo;
    cudaGetSymbolAddress((void**)&xhi,  g_xhi);
    cudaGetSymbolAddress((void**)&xlo,  g_xlo);
    cudaGetSymbolAddress((void**)&hhi,  g_hhi);
    cudaGetSymbolAddress((void**)&hlo,  g_hlo);
    cudaGetSymbolAddress((void**)&b1hi, g_B1hi);
    cudaGetSymbolAddress((void**)&b1lo, g_B1lo);
    cudaGetSymbolAddress((void**)&b2hi, g_B2hi);
    cudaGetSymbolAddress((void**)&b2lo, g_B2lo);

    cudaFuncSetAttribute(gemm_mma_kernel,
                         cudaFuncAttributeMaxDynamicSharedMemorySize, GEMM_SMEM);

    // --- operand conversions (independent of CSR) ---
    int nx = n * FEAT;
    conv_split_kernel<<<(nx + 255) / 256, 256>>>(x, xhi, xlo, nx);
    convW1_kernel<<<FEAT * FEAT / 256, 256>>>(W1);
    convW2_kernel<<<FEAT * FEAT / 256, 256>>>(Wmu, Wls);

    // --- CSR build ---
    detect_kernel<<<1, 32>>>(ei, n, E);
    init_kernel<<<gN, TB>>>(n);
    count_kernel<<<gE, TB>>>(ei, E);
    dinv_kernel<<<gN, TB>>>(n);
    scan_block_kernel<<<nb, 1024>>>(n);
    scan_sums_kernel<<<1, 32>>>(nb);
    scan_add_kernel<<<gN, TB>>>(n, E);
    scatter_kernel<<<gE, TB>>>(ei, E);

    dim3 gg((n + GBM - 1) / GBM, FEAT / GBN);

    // --- Layer 1: h0 = x @ W1 (HMMA) ; h = relu(agg(h0)+b1) split ---
    gemm_mma_kernel<<<gg, 256, GEMM_SMEM>>>(xhi, xlo, b1hi, b1lo, h0, n);
    agg1_kernel<<<n, FEAT>>>(b1, n);

    // --- Layer 2: h0 = h @ [Wmu|Wls] (single N=256 GEMM) ---
    gemm_mma_kernel<<<gg, 256, GEMM_SMEM>>>(hhi, hlo, b2hi, b2lo, h0, n);

    // --- Final aggregation straight into d_out (mu | logstd) ---
    agg2_kernel<<<n, FEAT>>>(bmu, bls, out, n);
}

// round 6
// speedup vs baseline: 1.4198x; 1.0687x over previous
#include <cuda_runtime.h>
#include <cuda_bf16.h>
#include <cstdint>

// Problem constants (fixed shapes for this problem instance)
#define MAXN 50000
#define MAXE 800000
#define FEAT 256          // IN_C = HID = 256 (and 2*OUT_C = 256)
#define OUTC 128

// ---------------------------------------------------------------------------
// Static device scratch (no dynamic allocation allowed)
// ---------------------------------------------------------------------------
__device__ float g_h0[(size_t)MAXN * FEAT];          // GEMM outputs (fp32, agg input)
__device__ __nv_bfloat16 g_xhi[(size_t)MAXN * FEAT]; // split x
__device__ __nv_bfloat16 g_xlo[(size_t)MAXN * FEAT];
__device__ __nv_bfloat16 g_hhi[(size_t)MAXN * FEAT]; // split hidden (post agg1)
__device__ __nv_bfloat16 g_hlo[(size_t)MAXN * FEAT];
__device__ __nv_bfloat16 g_B1hi[FEAT * FEAT];        // W1^T split  [n][k]
__device__ __nv_bfloat16 g_B1lo[FEAT * FEAT];
__device__ __nv_bfloat16 g_B2hi[FEAT * FEAT];        // [Wmu|Wls]^T split [n][k]
__device__ __nv_bfloat16 g_B2lo[FEAT * FEAT];
__device__ float g_dinv[MAXN];
__device__ int   g_count[MAXN];
__device__ int   g_rowptr[MAXN + 1];
__device__ int   g_cursor[MAXN];
__device__ int   g_col[MAXE];
__device__ float g_val[MAXE];
__device__ int   g_bsums[64];
__device__ int   g_is64;

// ---------------------------------------------------------------------------
// PTX helpers: ldmatrix + bf16 mma + cp.async (portable to compute_103)
// ---------------------------------------------------------------------------
__device__ __forceinline__ uint32_t smem_u32(const void* p)
{
    uint32_t a;
    asm("{ .reg .u64 t; cvta.to.shared.u64 t, %1; cvt.u32.u64 %0, t; }"
        : "=r"(a) : "l"(p));
    return a;
}

#define LDSM_X4(r, addr)                                                        \
    asm volatile("ldmatrix.sync.aligned.m8n8.x4.shared.b16 {%0,%1,%2,%3}, [%4];"\
        : "=r"((r)[0]), "=r"((r)[1]), "=r"((r)[2]), "=r"((r)[3])                \
        : "r"(addr))

#define MMA_BF16(c, a, b0, b1)                                                  \
    asm volatile("mma.sync.aligned.m16n8k16.row.col.f32.bf16.bf16.f32 "         \
        "{%0,%1,%2,%3}, {%4,%5,%6,%7}, {%8,%9}, {%0,%1,%2,%3};"                 \
        : "+f"((c)[0]), "+f"((c)[1]), "+f"((c)[2]), "+f"((c)[3])                \
        : "r"((a)[0]), "r"((a)[1]), "r"((a)[2]), "r"((a)[3]),                   \
          "r"(b0), "r"(b1))

// 16B async copy, zero-fill when sz==0 (src not dereferenced)
#define CP_ASYNC16(dst, src, sz)                                                \
    asm volatile("cp.async.cg.shared.global [%0], [%1], 16, %2;"                \
        :: "r"(dst), "l"(src), "r"(sz))
#define CP_COMMIT() asm volatile("cp.async.commit_group;" ::: "memory")
#define CP_WAIT(N)  asm volatile("cp.async.wait_group %0;" :: "n"(N) : "memory")

#define SWZ128(o) ((o) ^ (((o) >> 3) & 0x70))

// ---------------------------------------------------------------------------
// Edge-index dtype detection (int64 vs int32; JAX may truncate int64->int32)
// ---------------------------------------------------------------------------
__global__ void detect_kernel(const void* ei, int n, int E)
{
    __shared__ int ok;
    if (threadIdx.x == 0) ok = 1;
    __syncthreads();
    const long long* p64 = (const long long*)ei;
    int m = 2048;
    if (E < m) m = E;
    for (int i = threadIdx.x; i < m; i += blockDim.x) {
        long long v = p64[i];
        if (v < 0 || v >= (long long)n) ok = 0;   // benign race: only writes 0
    }
    __syncthreads();
    if (threadIdx.x == 0) g_is64 = ok;
}

__device__ __forceinline__ int edge_at(const void* ei, int idx)
{
    if (g_is64) return (int)((const long long*)ei)[idx];
    return ((const int*)ei)[idx];
}

// ---------------------------------------------------------------------------
// CSR build
// ---------------------------------------------------------------------------
__global__ void init_kernel(int n)
{
    int i = blockIdx.x * blockDim.x + threadIdx.x;
    if (i < n) g_count[i] = 0;
}

__global__ void count_kernel(const void* ei, int E)
{
    int e = blockIdx.x * blockDim.x + threadIdx.x;
    if (e < E) {
        int d = edge_at(ei, E + e);
        atomicAdd(&g_count[d], 1);
    }
}

__global__ void dinv_kernel(int n)
{
    int i = blockIdx.x * blockDim.x + threadIdx.x;
    if (i < n) g_dinv[i] = rsqrtf((float)g_count[i] + 1.0f);
}

__global__ void scan_block_kernel(int n)
{
    __shared__ int s[1024];
    int b = blockIdx.x;
    int i = b * 1024 + threadIdx.x;
    int v = (i < n) ? g_count[i] : 0;
    s[threadIdx.x] = v;
    __syncthreads();
    for (int off = 1; off < 1024; off <<= 1) {
        int t = (threadIdx.x >= off) ? s[threadIdx.x - off] : 0;
        __syncthreads();
        s[threadIdx.x] += t;
        __syncthreads();
    }
    if (i < n) g_rowptr[i] = s[threadIdx.x] - v;
    if (threadIdx.x == 1023) g_bsums[b] = s[1023];
}

__global__ void scan_sums_kernel(int nb)
{
    if (threadIdx.x == 0 && blockIdx.x == 0) {
        int run = 0;
        for (int b = 0; b < nb; ++b) { int t = g_bsums[b]; g_bsums[b] = run; run += t; }
    }
}

__global__ void scan_add_kernel(int n, int E)
{
    int i = blockIdx.x * blockDim.x + threadIdx.x;
    if (i < n) {
        int r = g_rowptr[i] + g_bsums[i / 1024];
        g_rowptr[i] = r;
        g_cursor[i] = r;
    }
    if (i == 0) g_rowptr[n] = E;
}

__global__ void scatter_kernel(const void* ei, int E)
{
    int e = blockIdx.x * blockDim.x + threadIdx.x;
    if (e < E) {
        int s = edge_at(ei, e);
        int d = edge_at(ei, E + e);
        int p = atomicAdd(&g_cursor[d], 1);
        g_col[p] = s;
        g_val[p] = g_dinv[s] * g_dinv[d];
    }
}

// ---------------------------------------------------------------------------
// fp32 -> bf16 hi/lo split kernels
// ---------------------------------------------------------------------------
__global__ void conv_split_kernel(const float* __restrict__ a,
                                  __nv_bfloat16* __restrict__ hi,
                                  __nv_bfloat16* __restrict__ lo, int n)
{
    int i = blockIdx.x * blockDim.x + threadIdx.x;
    if (i < n) {
        float v = a[i];
        __nv_bfloat16 h = __float2bfloat16(v);
        hi[i] = h;
        lo[i] = __float2bfloat16(v - __bfloat162float(h));
    }
}

// W1 [k=256][n=256] row-major -> B1 [n][k] bf16 hi/lo
__global__ void convW1_kernel(const float* __restrict__ W1)
{
    int idx = blockIdx.x * blockDim.x + threadIdx.x;   // 65536
    int k = idx >> 8, n = idx & 255;
    float v = W1[idx];
    __nv_bfloat16 h = __float2bfloat16(v);
    g_B1hi[n * FEAT + k] = h;
    g_B1lo[n * FEAT + k] = __float2bfloat16(v - __bfloat162float(h));
}

// [Wmu | Wls] concat -> B2 [n(0..255)][k] hi/lo
__global__ void convW2_kernel(const float* __restrict__ Wmu, const float* __restrict__ Wls)
{
    int idx = blockIdx.x * blockDim.x + threadIdx.x;   // 65536
    int k = idx >> 8, n = idx & 255;
    float v = (n < OUTC) ? Wmu[k * OUTC + n] : Wls[k * OUTC + (n - OUTC)];
    __nv_bfloat16 h = __float2bfloat16(v);
    g_B2hi[n * FEAT + k] = h;
    g_B2lo[n * FEAT + k] = __float2bfloat16(v - __bfloat162float(h));
}

// ---------------------------------------------------------------------------
// HMMA GEMM (cp.async double-buffered):
// C[M x 256] = (Ahi+Alo) @ (Bhi+Blo)^T  (B stored [n][k])
// CTA tile 128x128, BK=64, 2-stage pipeline, 3-term bf16 split, fp32 accum.
// 8 warps: warp_m = w&3 (32 rows), warp_n = w>>2 (64 cols).
// grid = (ceil(M/128), 2). Dynamic smem = 128 KB (2 stages x 4 x 16KB).
// ---------------------------------------------------------------------------
#define GBM 128
#define GBN 128
#define GBK 64
#define STG 65536
#define SM_AH 0
#define SM_AL 16384
#define SM_BH 32768
#define SM_BL 49152
#define GEMM_SMEM 131072

__global__ __launch_bounds__(256, 1) void gemm_mma_kernel(
    const __nv_bfloat16* __restrict__ Ahi, const __nv_bfloat16* __restrict__ Alo,
    const __nv_bfloat16* __restrict__ Bhi, const __nv_bfloat16* __restrict__ Blo,
    float* __restrict__ C, int M)
{
    extern __shared__ char smem[];
    uint32_t sb = smem_u32(smem);
    int tid  = threadIdx.x;
    int lane = tid & 31;
    int w    = tid >> 5;
    int bm = blockIdx.x * GBM;
    int bn = blockIdx.y * GBN;
    int wm = (w & 3) * 32;
    int wn = (w >> 2) * 64;

    // per-thread load assignment: 4 chunks of 16B per tile per stage
    uint32_t soff[4];
    uint32_t asz[4];
    size_t   aoff[4], boff[4];
#pragma unroll
    for (int t = 0; t < 4; ++t) {
        int idx = tid + t * 256;           // 0..1023
        int row = idx >> 3;                // 0..127
        int ch  = idx & 7;                 // 16B chunk in 128B row
        soff[t] = SWZ128(row * 128 + ch * 16);
        int gr = bm + row;
        asz[t]  = (gr < M) ? 16u : 0u;
        int grc = (gr < M) ? gr : 0;       // clamped (unread when sz=0)
        aoff[t] = (size_t)grc * FEAT + ch * 8;
        boff[t] = (size_t)(bn + row) * FEAT + ch * 8;
    }

    // ldmatrix lane address pre-offsets (unswizzled)
    int a_pre[2];
    {
        int r = wm + ((lane >> 3) & 1) * 8 + (lane & 7);
        int kb = (lane >> 4) * 16;
        a_pre[0] = r * 128 + kb;
        a_pre[1] = (r + 16) * 128 + kb;
    }
    int b_pre[4];
    {
        int r = wn + ((lane >> 4) & 1) * 8 + (lane & 7);
        int kb = ((lane >> 3) & 1) * 16;
#pragma unroll
        for (int nf2 = 0; nf2 < 4; ++nf2)
            b_pre[nf2] = (r + nf2 * 16) * 128 + kb;
    }

    float acc[2][8][4];
#pragma unroll
    for (int i = 0; i < 2; ++i)
#pragma unroll
        for (int j = 0; j < 8; ++j)
#pragma unroll
            for (int q = 0; q < 4; ++q) acc[i][j][q] = 0.0f;

    // ---- pipeline: issue stage for k-chunk kc into buffer kc&1 ----
#define ISSUE_STAGE(kc) do {                                                    \
    uint32_t base = sb + (uint32_t)((kc) & 1) * STG;                            \
    int k0 = (kc) * GBK;                                                        \
    _Pragma("unroll")                                                           \
    for (int t = 0; t < 4; ++t) {                                               \
        CP_ASYNC16(base + SM_AH + soff[t], (const char*)(Ahi + aoff[t] + k0), asz[t]); \
        CP_ASYNC16(base + SM_AL + soff[t], (const char*)(Alo + aoff[t] + k0), asz[t]); \
        CP_ASYNC16(base + SM_BH + soff[t], (const char*)(Bhi + boff[t] + k0), 16u);    \
        CP_ASYNC16(base + SM_BL + soff[t], (const char*)(Blo + boff[t] + k0), 16u);    \
    }                                                                           \
    CP_COMMIT();                                                                \
} while (0)

    ISSUE_STAGE(0);

    for (int kc = 0; kc < 4; ++kc) {
        if (kc < 3) { ISSUE_STAGE(kc + 1); CP_WAIT(1); }
        else        { CP_WAIT(0); }
        __syncthreads();

        uint32_t base = sb + (uint32_t)(kc & 1) * STG;
#pragma unroll
        for (int ks = 0; ks < 4; ++ks) {
            int kb = ks * 32;
            uint32_t ah[2][4], al[2][4], bh[4][4], bl[4][4];
#pragma unroll
            for (int mf = 0; mf < 2; ++mf) {
                uint32_t o = SWZ128(a_pre[mf] + kb);
                LDSM_X4(ah[mf], base + SM_AH + o);
                LDSM_X4(al[mf], base + SM_AL + o);
            }
#pragma unroll
            for (int nf2 = 0; nf2 < 4; ++nf2) {
                uint32_t o = SWZ128(b_pre[nf2] + kb);
                LDSM_X4(bh[nf2], base + SM_BH + o);
                LDSM_X4(bl[nf2], base + SM_BL + o);
            }
#pragma unroll
            for (int mf = 0; mf < 2; ++mf) {
#pragma unroll
                for (int nf2 = 0; nf2 < 4; ++nf2) {
                    MMA_BF16(acc[mf][nf2 * 2],     ah[mf], bh[nf2][0], bh[nf2][1]);
                    MMA_BF16(acc[mf][nf2 * 2 + 1], ah[mf], bh[nf2][2], bh[nf2][3]);
                    MMA_BF16(acc[mf][nf2 * 2],     ah[mf], bl[nf2][0], bl[nf2][1]);
                    MMA_BF16(acc[mf][nf2 * 2 + 1], ah[mf], bl[nf2][2], bl[nf2][3]);
                    MMA_BF16(acc[mf][nf2 * 2],     al[mf], bh[nf2][0], bh[nf2][1]);
                    MMA_BF16(acc[mf][nf2 * 2 + 1], al[mf], bh[nf2][2], bh[nf2][3]);
                }
            }
        }
        __syncthreads();   // protect buffer reuse (issued at next iteration)
    }

    // epilogue: accumulator lane layout -> direct gmem stores (float2)
    int g  = lane >> 2;
    int cc = (lane & 3) * 2;
#pragma unroll
    for (int mf = 0; mf < 2; ++mf) {
#pragma unroll
        for (int nf = 0; nf < 8; ++nf) {
            int row = bm + wm + mf * 16 + g;
            int col = bn + wn + nf * 8 + cc;
            if (row < M) {
                float2 v0 = make_float2(acc[mf][nf][0], acc[mf][nf][1]);
                *(float2*)&C[(size_t)row * FEAT + col] = v0;
            }
            if (row + 8 < M) {
                float2 v1 = make_float2(acc[mf][nf][2], acc[mf][nf][3]);
                *(float2*)&C[(size_t)(row + 8) * FEAT + col] = v1;
            }
        }
    }
}

// ---------------------------------------------------------------------------
// Aggregation: one block per node, 256 threads = 256 feature channels.
// out[i][c] = sum_{e in CSR row i} val[e]*h[col[e]][c] + dinv[i]^2*h[i][c]
// agg1 adds b1 + relu and writes bf16 hi/lo for the next GEMM.
// agg2 splits into mu / logstd halves of d_out.
// ---------------------------------------------------------------------------
__global__ void agg1_kernel(const float* __restrict__ b1, int n)
{
    int i = blockIdx.x;
    int c = threadIdx.x;
    float di = g_dinv[i];
    float a0 = di * di * g_h0[(size_t)i * FEAT + c];
    float a1 = 0.0f, a2 = 0.0f, a3 = 0.0f;
    int e0 = g_rowptr[i], e1 = g_rowptr[i + 1];
    int e = e0;
    for (; e + 3 < e1; e += 4) {
        int s0 = g_col[e];     float w0 = g_val[e];
        int s1 = g_col[e + 1]; float w1 = g_val[e + 1];
        int s2 = g_col[e + 2]; float w2 = g_val[e + 2];
        int s3 = g_col[e + 3]; float w3 = g_val[e + 3];
        a0 += w0 * g_h0[(size_t)s0 * FEAT + c];
        a1 += w1 * g_h0[(size_t)s1 * FEAT + c];
        a2 += w2 * g_h0[(size_t)s2 * FEAT + c];
        a3 += w3 * g_h0[(size_t)s3 * FEAT + c];
    }
    for (; e < e1; ++e) {
        int s = g_col[e]; float w = g_val[e];
        a0 += w * g_h0[(size_t)s * FEAT + c];
    }
    float r = fmaxf((a0 + a1) + (a2 + a3) + b1[c], 0.0f);
    __nv_bfloat16 h = __float2bfloat16(r);
    g_hhi[(size_t)i * FEAT + c] = h;
    g_hlo[(size_t)i * FEAT + c] = __float2bfloat16(r - __bfloat162float(h));
}

__global__ void agg2_kernel(const float* __restrict__ bmu,
                            const float* __restrict__ bls,
                            float* __restrict__ out, int n)
{
    int i = blockIdx.x;
    int c = threadIdx.x;
    float di = g_dinv[i];
    float a0 = di * di * g_h0[(size_t)i * FEAT + c];
    float a1 = 0.0f, a2 = 0.0f, a3 = 0.0f;
    int e0 = g_rowptr[i], e1 = g_rowptr[i + 1];
    int e = e0;
    for (; e + 3 < e1; e += 4) {
        int s0 = g_col[e];     float w0 = g_val[e];
        int s1 = g_col[e + 1]; float w1 = g_val[e + 1];
        int s2 = g_col[e + 2]; float w2 = g_val[e + 2];
        int s3 = g_col[e + 3]; float w3 = g_val[e + 3];
        a0 += w0 * g_h0[(size_t)s0 * FEAT + c];
        a1 += w1 * g_h0[(size_t)s1 * FEAT + c];
        a2 += w2 * g_h0[(size_t)s2 * FEAT + c];
        a3 += w3 * g_h0[(size_t)s3 * FEAT + c];
    }
    for (; e < e1; ++e) {
        int s = g_col[e]; float w = g_val[e];
        a0 += w * g_h0[(size_t)s * FEAT + c];
    }
    float r = (a0 + a1) + (a2 + a3);
    if (c < OUTC) {
        out[(size_t)i * OUTC + c] = r + bmu[c];
    } else {
        out[(size_t)n * OUTC + (size_t)i * OUTC + (c - OUTC)] = r + bls[c - OUTC];
    }
}

// ---------------------------------------------------------------------------
// Launch
// ---------------------------------------------------------------------------
extern "C" void kernel_launch(void* const* d_in, const int* in_sizes, int n_in,
                              void* d_out, int out_size)
{
    const float* x    = (const float*)d_in[0];
    const void*  ei   = d_in[1];
    const float* W1   = (const float*)d_in[2];
    const float* b1   = (const float*)d_in[3];
    const float* Wmu  = (const float*)d_in[4];
    const float* bmu  = (const float*)d_in[5];
    const float* Wls  = (const float*)d_in[6];
    const float* bls  = (const float*)d_in[7];
    float* out = (float*)d_out;

    int n = in_sizes[0] / FEAT;      // 50000
    int E = in_sizes[1] / 2;         // 800000

    int TB = 256;
    int gN = (n + TB - 1) / TB;
    int gE = (E + TB - 1) / TB;
    int nb = (n + 1023) / 1024;

    float* h0;  cudaGetSymbolAddress((void**)&h0,  g_h0);
    __nv_bfloat16 *xhi, *xlo, *hhi, *hlo, *b1hi, *b1lo, *b2hi, *b2lo;
    cudaGetSymbolAddress((void**)&xhi,  g_xhi);
    cudaGetSymbolAddress((void**)&xlo,  g_xlo);
    cudaGetSymbolAddress((void**)&hhi,  g_hhi);
    cudaGetSymbolAddress((void**)&hlo,  g_hlo);
    cudaGetSymbolAddress((void**)&b1hi, g_B1hi);
    cudaGetSymbolAddress((void**)&b1lo, g_B1lo);
    cudaGetSymbolAddress((void**)&b2hi, g_B2hi);
    cudaGetSymbolAddress((void**)&b2lo, g_B2lo);

    cudaFuncSetAttribute(gemm_mma_kernel,
                         cudaFuncAttributeMaxDynamicSharedMemorySize, GEMM_SMEM);

    // --- operand conversions (independent of CSR) ---
    int nx = n * FEAT;
    conv_split_kernel<<<(nx + 255) / 256, 256>>>(x, xhi, xlo, nx);
    convW1_kernel<<<FEAT * FEAT / 256, 256>>>(W1);
    convW2_kernel<<<FEAT * FEAT / 256, 256>>>(Wmu, Wls);

    // --- CSR build ---
    detect_kernel<<<1, 256>>>(ei, n, E);
    init_kernel<<<gN, TB>>>(n);
    count_kernel<<<gE, TB>>>(ei, E);
    dinv_kernel<<<gN, TB>>>(n);
    scan_block_kernel<<<nb, 1024>>>(n);
    scan_sums_kernel<<<1, 32>>>(nb);
    scan_add_kernel<<<gN, TB>>>(n, E);
    scatter_kernel<<<gE, TB>>>(ei, E);

    dim3 gg((n + GBM - 1) / GBM, FEAT / GBN);

    // --- Layer 1: h0 = x @ W1 (HMMA, pipelined) ; h = relu(agg(h0)+b1) ---
    gemm_mma_kernel<<<gg, 256, GEMM_SMEM>>>(xhi, xlo, b1hi, b1lo, h0, n);
    agg1_kernel<<<n, FEAT>>>(b1, n);

    // --- Layer 2: h0 = h @ [Wmu|Wls] (single N=256 GEMM) ---
    gemm_mma_kernel<<<gg, 256, GEMM_SMEM>>>(hhi, hlo, b2hi, b2lo, h0, n);

    // --- Final aggregation straight into d_out (mu | logstd) ---
    agg2_kernel<<<n, FEAT>>>(bmu, bls, out, n);
}